// round 11
// baseline (speedup 1.0000x reference)
#include <cuda_runtime.h>

#define BB 4
#define NN 512
#define MM 512
#define DD 128
#define TN 64
#define TM 32

typedef unsigned long long u64;
typedef unsigned int u32;

// ---------------- device scratch (no allocations allowed) ----------------
__device__ float g_z [BB * NN * MM];     // 4 MB z[b][n][m]
__device__ float g_zt[BB * MM * NN];     // 4 MB z^T[b][m][n]
__device__ u32   g_rEnc[BB * NN];        // zero-init; enc-min accumulators
__device__ u32   g_cEnc[BB * MM];        //   (reset by k_stats each launch)
__device__ float g_rmin[BB * NN];
__device__ float g_rinv[BB * NN];
__device__ float g_cmin[BB * MM];
__device__ float g_cinv[BB * MM];
__device__ float g_pnum[BB * NN];
__device__ float g_pden[BB * NN];
__device__ int   g_cnt[BB];

// int32-vs-int64 length sniff (jax canonicalization)
__device__ __forceinline__ int load_len(const void* p, int i) {
    const unsigned* u = (const unsigned*)p;
    if (u[1] == 0u) return (int)((const long long*)p)[i];
    return ((const int*)p)[i];
}

// enc: monotone-DECREASING map of non-negative floats onto u32 so that
// max(enc) == enc(min). z >= 0 always. Exact, order-invariant, deterministic.
__device__ __forceinline__ u32 encf(float f) { return ~__float_as_uint(f); }
__device__ __forceinline__ float decf(u32 e) { return __uint_as_float(~e); }

// ---------------- packed f32x2 helpers (Blackwell) ----------------
__device__ __forceinline__ u64 pk2(float lo, float hi) {
    u64 r; asm("mov.b64 %0, {%1, %2};" : "=l"(r) : "f"(lo), "f"(hi)); return r;
}
__device__ __forceinline__ u64 add2(u64 a, u64 b) {
    u64 r; asm("add.rn.f32x2 %0, %1, %2;" : "=l"(r) : "l"(a), "l"(b)); return r;
}
__device__ __forceinline__ void upk2(u64 v, float& lo, float& hi) {
    asm("mov.b64 {%0, %1}, %2;" : "=f"(lo), "=f"(hi) : "l"(v));
}

// ---------------- kernel 1: pairwise L1 distance (best R4 shape) ---------
// Grid (16, 8, 4) = 512 blocks; 256 threads; 64n x 32m tile, 4n x 2m micro,
// n-packed accumulators (19.3us measured shape). Adds: z^T store + exact
// row/col min side-channel via smem atomicMax on enc values.
__global__ __launch_bounds__(256) void k_zdiff(
    const float* __restrict__ x, const float* __restrict__ y,
    const void* __restrict__ xlen, const void* __restrict__ ylen) {
    if (blockIdx.x == 0 && blockIdx.y == 0 && blockIdx.z == 0 && threadIdx.x < BB)
        g_cnt[threadIdx.x] = 0;

    int b = blockIdx.z;
    int n0 = blockIdx.y * TN;
    int m0 = blockIdx.x * TM;
    int xl = load_len(xlen, b);
    int yl = load_len(ylen, b);
    if (n0 >= xl || m0 >= yl) return;

    __shared__ float xs[64 * TN];   // 16 KB [d][n]
    __shared__ float ys[64 * TM];   // 8 KB  [d][m], NEGATED y
    __shared__ u32 rEnc[TN];
    __shared__ u32 cEnc[TM];

    int tid = threadIdx.x;
    int ty = tid >> 4;      // 0..15 -> n micro-group (4 rows)
    int tx = tid & 15;      // 0..15 -> m micro-group (2 cols)

    if (tid < TN) rEnc[tid] = 0;
    else if (tid < TN + TM) cEnc[tid - TN] = 0;

    const float* xb = x + ((size_t)b * NN + n0) * DD;
    const float* yb = y + ((size_t)b * MM + m0) * DD;

    u64 acc[2][2];          // [n-pair][m]
    acc[0][0] = acc[0][1] = acc[1][0] = acc[1][1] = 0ull;

    const u64 ABSM = 0x7FFFFFFF7FFFFFFFull;

#pragma unroll
    for (int p = 0; p < 2; p++) {
        // stage x: 64 n x 64 d transposed
#pragma unroll
        for (int it = 0; it < 4; it++) {
            int idx = tid + 256 * it;           // 0..1023
            int n  = idx & 63;
            int dq = idx >> 6;                  // 0..15
            const float4 vx = *(const float4*)(xb + (size_t)n * DD + p * 64 + dq * 4);
            xs[(dq * 4 + 0) * TN + n] = vx.x;
            xs[(dq * 4 + 1) * TN + n] = vx.y;
            xs[(dq * 4 + 2) * TN + n] = vx.z;
            xs[(dq * 4 + 3) * TN + n] = vx.w;
        }
        // stage y negated: 32 m x 64 d transposed
#pragma unroll
        for (int it = 0; it < 2; it++) {
            int idx = tid + 256 * it;           // 0..511
            int m  = idx & 31;
            int dq = idx >> 5;                  // 0..15
            const float4 vy = *(const float4*)(yb + (size_t)m * DD + p * 64 + dq * 4);
            ys[(dq * 4 + 0) * TM + m] = -vy.x;
            ys[(dq * 4 + 1) * TM + m] = -vy.y;
            ys[(dq * 4 + 2) * TM + m] = -vy.z;
            ys[(dq * 4 + 3) * TM + m] = -vy.w;
        }
        __syncthreads();

#pragma unroll 8
        for (int d = 0; d < 64; d++) {
            ulonglong2 lx = *(const ulonglong2*)(xs + d * TN + ty * 4);  // n-pairs
            float2 ln = *(const float2*)(ys + d * TM + tx * 2);          // -y[m], -y[m+1]
            u64 d0 = pk2(ln.x, ln.x);
            u64 d1 = pk2(ln.y, ln.y);
            u64 t00 = add2(lx.x, d0) & ABSM;
            u64 t10 = add2(lx.y, d0) & ABSM;
            u64 t01 = add2(lx.x, d1) & ABSM;
            u64 t11 = add2(lx.y, d1) & ABSM;
            acc[0][0] = add2(acc[0][0], t00);
            acc[1][0] = add2(acc[1][0], t10);
            acc[0][1] = add2(acc[0][1], t01);
            acc[1][1] = add2(acc[1][1], t11);
        }
        __syncthreads();
    }

    // unpack: acc[i][j] = rows (2i, 2i+1) x col j
    float a00l, a00h, a01l, a01h, a10l, a10h, a11l, a11h;
    upk2(acc[0][0], a00l, a00h);
    upk2(acc[0][1], a01l, a01h);
    upk2(acc[1][0], a10l, a10h);
    upk2(acc[1][1], a11l, a11h);

    // z store: 4 n-rows x float2
    float* zb = g_z + ((size_t)b * NN + n0 + ty * 4) * MM + m0 + tx * 2;
    *(float2*)(zb + 0 * MM) = make_float2(a00l, a01l);
    *(float2*)(zb + 1 * MM) = make_float2(a00h, a01h);
    *(float2*)(zb + 2 * MM) = make_float2(a10l, a11l);
    *(float2*)(zb + 3 * MM) = make_float2(a10h, a11h);

    // z^T store: 2 m-rows x float4
    float* ztb = g_zt + ((size_t)b * MM + m0 + tx * 2) * NN + n0 + ty * 4;
    *(float4*)(ztb + 0 * NN) = make_float4(a00l, a00h, a10l, a10h);
    *(float4*)(ztb + 1 * NN) = make_float4(a01l, a01h, a11l, a11h);

    // exact row/col mins via smem atomicMax on enc (max enc == min z)
    atomicMax(&rEnc[ty * 4 + 0], encf(fminf(a00l, a01l)));
    atomicMax(&rEnc[ty * 4 + 1], encf(fminf(a00h, a01h)));
    atomicMax(&rEnc[ty * 4 + 2], encf(fminf(a10l, a11l)));
    atomicMax(&rEnc[ty * 4 + 3], encf(fminf(a10h, a11h)));
    atomicMax(&cEnc[tx * 2 + 0], encf(fminf(fminf(a00l, a00h), fminf(a10l, a10h))));
    atomicMax(&cEnc[tx * 2 + 1], encf(fminf(fminf(a01l, a01h), fminf(a11l, a11h))));
    __syncthreads();
    if (tid < TN)                atomicMax(&g_rEnc[b * NN + n0 + tid], rEnc[tid]);
    else if (tid < TN + TM)      atomicMax(&g_cEnc[b * MM + m0 + tid - TN], cEnc[tid - TN]);
}

// ---------------- kernel 2: single-pass softmax denominators -------------
// 512 blocks x 256 threads, 8 warps/block -> 4096 warp-rows.
//   w in [0,2048):    z rows   (b, n): expsum over yl -> rmin/rinv
//   w in [2048,4096): z^T rows (b, m): expsum over xl -> cmin/cinv
// Min comes precomputed from k_zdiff's enc buffers (reset here for next call).
__global__ __launch_bounds__(256) void k_stats(
    const void* __restrict__ xlen, const void* __restrict__ ylen) {
    int w = blockIdx.x * 8 + (threadIdx.x >> 5);
    int lane = threadIdx.x & 31;

    const float* src;
    float* omin; float* oinv; u32* encp;
    int len; bool valid;
    if (w < 2048) {
        int b = w >> 9, n = w & 511;
        valid = n < load_len(xlen, b);
        len = load_len(ylen, b);
        src = g_z + ((size_t)b * NN + n) * MM;
        encp = &g_rEnc[b * NN + n];
        omin = g_rmin + b * NN + n;
        oinv = g_rinv + b * NN + n;
    } else {
        int w2 = w - 2048;
        int b = w2 >> 9, m = w2 & 511;
        valid = m < load_len(ylen, b);
        len = load_len(xlen, b);
        src = g_zt + ((size_t)b * MM + m) * NN;
        encp = &g_cEnc[b * MM + m];
        omin = g_cmin + b * MM + m;
        oinv = g_cinv + b * MM + m;
    }

    u32 e = *(volatile u32*)encp;       // broadcast load
    if (lane == 0) *encp = 0;           // reset for next launch (deterministic)
    if (!valid) return;
    float zmin = decf(e);

    const float4* s4 = (const float4*)src;
    int nv4 = len >> 2;
    int base = len & ~3;

    float s = 0.0f;
#pragma unroll 4
    for (int i = lane; i < nv4; i += 32) {
        float4 v = s4[i];
        s += __expf(zmin - v.x) + __expf(zmin - v.y)
           + __expf(zmin - v.z) + __expf(zmin - v.w);
    }
    if (base + lane < len) s += __expf(zmin - src[base + lane]);
#pragma unroll
    for (int o = 16; o; o >>= 1) s += __shfl_xor_sync(0xffffffffu, s, o);

    if (lane == 0) {
        *omin = zmin;
        *oinv = 1.0f / s;
    }
}

// ---------------- kernel 3: combine + fused final reduction --------------
// 512 blocks x 128 threads; warp per (b,n) row; last block per batch reduces.
__global__ __launch_bounds__(128) void k_accum(
    const void* __restrict__ xlen, const void* __restrict__ ylen,
    float* __restrict__ out) {
    int blk = blockIdx.x;
    int tid = threadIdx.x;
    int lane = tid & 31;
    int wid  = tid >> 5;
    int b = blk >> 7;
    int n = (blk & 127) * 4 + wid;
    int xl = load_len(xlen, b);
    int yl = load_len(ylen, b);

    if (n < xl) {
        const float*  zr  = g_z + ((size_t)b * NN + n) * MM;
        const float4* z4  = (const float4*)zr;
        const float*  cmn = g_cmin + b * MM;
        const float*  civ = g_cinv + b * MM;
        const float4* cm4 = (const float4*)cmn;
        const float4* ci4 = (const float4*)civ;
        float rmin = g_rmin[b * NN + n];
        float rinv = g_rinv[b * NN + n];

        int nv4 = yl >> 2;
        int base = yl & ~3;

        float num = 0.0f, den = 0.0f;
#pragma unroll 4
        for (int i = lane; i < nv4; i += 32) {
            float4 z = z4[i];
            float4 cm = cm4[i];
            float4 ci = ci4[i];
            {
                float beta  = __expf(rmin - z.x) * rinv;
                float alpha = __expf(cm.x - z.x) * ci.x;
                float a = alpha + beta - alpha * beta;
                den += a; num += a * z.x;
            }
            {
                float beta  = __expf(rmin - z.y) * rinv;
                float alpha = __expf(cm.y - z.y) * ci.y;
                float a = alpha + beta - alpha * beta;
                den += a; num += a * z.y;
            }
            {
                float beta  = __expf(rmin - z.z) * rinv;
                float alpha = __expf(cm.z - z.z) * ci.z;
                float a = alpha + beta - alpha * beta;
                den += a; num += a * z.z;
            }
            {
                float beta  = __expf(rmin - z.w) * rinv;
                float alpha = __expf(cm.w - z.w) * ci.w;
                float a = alpha + beta - alpha * beta;
                den += a; num += a * z.w;
            }
        }
        if (base + lane < yl) {
            int m = base + lane;
            float z = zr[m];
            float beta  = __expf(rmin - z) * rinv;
            float alpha = __expf(cmn[m] - z) * civ[m];
            float a = alpha + beta - alpha * beta;
            den += a; num += a * z;
        }
#pragma unroll
        for (int o = 16; o; o >>= 1) {
            num += __shfl_xor_sync(0xffffffffu, num, o);
            den += __shfl_xor_sync(0xffffffffu, den, o);
        }
        if (lane == 0) {
            g_pnum[b * NN + n] = num;
            g_pden[b * NN + n] = den;
        }
    }

    // ---- last-block-done: fused final reduction (deterministic) ----
    __shared__ int s_last;
    __syncthreads();
    if (tid == 0) {
        __threadfence();
        int old = atomicAdd(&g_cnt[b], 1);
        s_last = (old == 127);
    }
    __syncthreads();
    if (!s_last) return;
    __threadfence();

    float num = 0.0f, den = 0.0f;
    for (int i = tid; i < xl; i += 128) {
        num += g_pnum[b * NN + i];
        den += g_pden[b * NN + i];
    }
    __shared__ float sn[128];
    __shared__ float sd[128];
    sn[tid] = num;
    sd[tid] = den;
    __syncthreads();
    for (int s2 = 64; s2; s2 >>= 1) {
        if (tid < s2) {
            sn[tid] += sn[tid + s2];
            sd[tid] += sd[tid + s2];
        }
        __syncthreads();
    }
    if (tid == 0) out[b] = -sn[0] / sd[0];
}

// ---------------- launch ----------------
extern "C" void kernel_launch(void* const* d_in, const int* in_sizes, int n_in,
                              void* d_out, int out_size) {
    const float* x = (const float*)d_in[0];
    const float* y = (const float*)d_in[1];
    const void* xl = d_in[2];
    const void* yl = d_in[3];
    float* out = (float*)d_out;

    dim3 g1(MM / TM, NN / TN, BB);          // (16, 8, 4) = 512 blocks
    k_zdiff<<<g1, 256>>>(x, y, xl, yl);
    k_stats<<<512, 256>>>(xl, yl);
    k_accum<<<512, 128>>>(xl, yl, out);
}